// round 15
// baseline (speedup 1.0000x reference)
#include <cuda_runtime.h>

#define FULLMASK 0xffffffffu
#define MAX_PATCHES 32768

__device__ float g_emb[MAX_PATCHES * 32];      // raw channel sums (mean*64)
__device__ unsigned int g_done[4];             // K1 blocks completed per chunk

__global__ void init_kernel() {
    if (threadIdx.x < 4) g_done[threadIdx.x] = 0u;
}

// Combined kernel. Blocks [0, k1_blocks): K1 streaming reduce (8 patches/blk,
// 1/warp, the 6.2 TB/s pattern). Blocks [k1_blocks, ...): K2 router math
// (4 threads/patch, 64 patches/blk) gated per-chunk on K1 completion counters.
// K2 blocks are at the grid tail -> scheduled as K1 retires -> true overlap
// inside ONE launch (same-stream kernels cannot overlap).
__global__ void __launch_bounds__(256, 6) fused_kernel(
    const float* __restrict__ patch,
    const float* __restrict__ keys,
    const float* __restrict__ p_temp,
    const float* __restrict__ p_beta,
    const float* __restrict__ p_thr,
    float* __restrict__ out,
    int n_patches, int k1_blocks, int cb /*K1 blocks per chunk*/, int k2bpc)
{
    const int bid = blockIdx.x;
    const int tid = threadIdx.x;

    if (bid < k1_blocks) {
        // ========================= K1: streaming reduce =========================
        const int wid  = tid >> 5;
        const int lane = tid & 31;
        const int n = bid * 8 + wid;
        if (n < n_patches) {
            const float4* p4 = reinterpret_cast<const float4*>(patch) + (size_t)n * 512;
            float4 v[16];
#pragma unroll
            for (int t = 0; t < 16; t++) {
                const int p = t >> 2, q = t & 3;
                v[t] = p4[p * 128 + (lane >> 2) * 16 + (lane & 3) + 4 * q];
            }
#pragma unroll
            for (int p = 0; p < 4; p++) {
                float a = 0.0f;
#pragma unroll
                for (int q = 0; q < 4; q++) {
                    const float4 x = v[p * 4 + q];
                    a += (x.x + x.y) + (x.z + x.w);
                }
                a += __shfl_xor_sync(FULLMASK, a, 1);
                a += __shfl_xor_sync(FULLMASK, a, 2);
                if ((lane & 3) == 0)
                    g_emb[n * 32 + p * 8 + (lane >> 2)] = a;
            }
        }
        __threadfence();          // my stores visible device-wide
        __syncthreads();          // all threads fenced
        if (tid == 0)
            atomicAdd(&g_done[bid / cb], 1u);
        return;
    }

    // =========================== K2: router math ===========================
    __shared__ float4 s_keys4[16][8];          // keys as float4 rows

    const int idx   = bid - k1_blocks;
    const int chunk = idx / k2bpc;
    const int bic   = idx % k2bpc;

    for (int i = tid; i < 16 * 8; i += 256)
        s_keys4[i >> 3][i & 7] = reinterpret_cast<const float4*>(keys)[i];

    // Wait for this chunk's K1 blocks (acquire; short spin since K2 blocks
    // are scheduled after their chunk's K1 blocks).
    const int target = min(cb, k1_blocks - chunk * cb);
    if (tid == 0) {
        unsigned v;
        do {
            asm volatile("ld.acquire.gpu.u32 %0, [%1];" : "=r"(v) : "l"(&g_done[chunk]));
            if ((int)v >= target) break;
            __nanosleep(128);
        } while (true);
    }
    __syncthreads();

    const int n = chunk * cb * 8 + bic * 64 + (tid >> 2);
    const int r = tid & 3;
    const int chunk_end = min(n_patches, (chunk + 1) * cb * 8);
    if (n >= chunk_end) return;

    const float logit_temp = __ldg(p_temp);
    const float mask_beta  = __ldg(p_beta);
    const float thr_base   = __ldg(p_thr);

    // Lane r owns channels 8r..8r+7 (2 x LDG.128, coalesced, non-redundant)
    const float4* g4 = reinterpret_cast<const float4*>(&g_emb[n * 32]) + r * 2;
    const float4 a0 = g4[0];
    const float4 a1 = g4[1];

    float sq = a0.x*a0.x + a0.y*a0.y + a0.z*a0.z + a0.w*a0.w
             + a1.x*a1.x + a1.y*a1.y + a1.z*a1.z + a1.w*a1.w;
    sq += __shfl_xor_sync(FULLMASK, sq, 1);
    sq += __shfl_xor_sync(FULLMASK, sq, 2);
    const float denom = fmaxf(sqrtf(sq), 64.0f * 1e-12f);

    // Partial dots for all 16 experts (float4 LDS: 2 per expert)
    float w[16];
#pragma unroll
    for (int e = 0; e < 16; e++) {
        const float4 k0 = s_keys4[e][r * 2];
        const float4 k1 = s_keys4[e][r * 2 + 1];
        float d = a0.x*k0.x + a0.y*k0.y + a0.z*k0.z + a0.w*k0.w
                + a1.x*k1.x + a1.y*k1.y + a1.z*k1.z + a1.w*k1.w;
        d += __shfl_xor_sync(FULLMASK, d, 1);
        d += __shfl_xor_sync(FULLMASK, d, 2);
        w[e] = (d / denom) / logit_temp + 1e-8f;
    }

    // Softmax over 16 (scalar, mirrored across the 4 lanes)
    float m = w[0];
#pragma unroll
    for (int e = 1; e < 16; e++) m = fmaxf(m, w[e]);
    float S = 0.0f;
#pragma unroll
    for (int e = 0; e < 16; e++) { w[e] = __expf(w[e] - m); S += w[e]; }
    const float invS = 1.0f / S;
#pragma unroll
    for (int e = 0; e < 16; e++) w[e] *= invS;

    // Top-5 via selection with exclusion bitmask
    float top[5];
    unsigned used = 0;
#pragma unroll
    for (int k = 0; k < 5; k++) {
        float best = -1.0f; int bi = 0;
#pragma unroll
        for (int e = 0; e < 16; e++) {
            const bool ok = !((used >> e) & 1u) && (w[e] > best);
            if (ok) { best = w[e]; bi = e; }
        }
        top[k] = best;
        used |= 1u << bi;
    }
    const float s0   = top[0];
    const float rest = (top[1] + top[2] + top[3] + top[4]) * 0.25f;
    const float kth  = top[3];

    // Moments & entropy
    float sum = 0.0f, ent = 0.0f;
#pragma unroll
    for (int e = 0; e < 16; e++) {
        sum += w[e];
        ent -= w[e] * __logf(w[e] + 1e-18f);
    }
    const float meanw = sum * (1.0f / 16.0f);
    float var = 0.0f;
#pragma unroll
    for (int e = 0; e < 16; e++) {
        const float d = w[e] - meanw;
        var = fmaf(d, d, var);
    }
    const float stdw = sqrtf(var * (1.0f / 15.0f));

    // Adaptive threshold
    const float maxc = 1.0f - s0;
    const float entc = 1.0f - ent * (1.0f / 2.7725887222397811f);
    float gap = (s0 - rest) / (s0 + 1e-8f);
    gap = fminf(fmaxf(gap, 0.0f), 1.0f);
    const float af = 0.4f * maxc + 0.3f * entc + 0.3f * gap;
    float adaptive = thr_base * (0.5f + af);
    const float min_thr = fmaxf(0.05f, meanw - 0.5f * stdw);
    const float max_thr = fminf(0.7f, s0 - 0.1f * stdw);
    adaptive = fminf(fmaxf(adaptive, min_thr), max_thr);
    adaptive = fminf(adaptive, kth * 0.9f);

    // Soft mask + renorm; lane writes its quarter (coalesced)
    float wf[16];
    float swf = 0.0f;
#pragma unroll
    for (int e = 0; e < 16; e++) {
        const float x  = (mask_beta + 1e-8f) * (w[e] - adaptive);
        const float sm = 1.0f / (1.0f + __expf(-x));
        wf[e] = w[e] * sm;
        swf += wf[e];
    }
    const float inv = 1.0f / fmaxf(swf, 1e-8f);

    float4 o;
    o.x = wf[r * 4 + 0] * inv; o.y = wf[r * 4 + 1] * inv;
    o.z = wf[r * 4 + 2] * inv; o.w = wf[r * 4 + 3] * inv;
    reinterpret_cast<float4*>(out + (size_t)n * 16)[r] = o;
}

extern "C" void kernel_launch(void* const* d_in, const int* in_sizes, int n_in,
                              void* d_out, int out_size) {
    const float* patch = (const float*)d_in[0];
    const float* keys  = (const float*)d_in[1];
    const float* temp  = (const float*)d_in[2];
    const float* beta  = (const float*)d_in[3];
    const float* thr   = (const float*)d_in[4];
    float* out = (float*)d_out;

    int n_patches = in_sizes[0] / (32 * 8 * 8);
    if (n_patches > MAX_PATCHES) n_patches = MAX_PATCHES;

    const int k1_blocks = (n_patches + 7) / 8;       // 4096 for N=32768
    const int cb        = (k1_blocks + 3) / 4;       // K1 blocks per chunk
    const int k2bpc     = (cb * 8 + 63) / 64;        // K2 blocks per chunk
    const int grid      = k1_blocks + 4 * k2bpc;

    init_kernel<<<1, 32>>>();
    fused_kernel<<<grid, 256>>>(patch, keys, temp, beta, thr, out,
                                n_patches, k1_blocks, cb, k2bpc);
}

// round 16
// speedup vs baseline: 1.1062x; 1.1062x over previous
#include <cuda_runtime.h>

#define FULLMASK 0xffffffffu
#define PATCHES_PER_WARP 8

__device__ __forceinline__ float redsum16(float v) {
    v += __shfl_xor_sync(FULLMASK, v, 8);
    v += __shfl_xor_sync(FULLMASK, v, 4);
    v += __shfl_xor_sync(FULLMASK, v, 2);
    v += __shfl_xor_sync(FULLMASK, v, 1);
    return v;
}
__device__ __forceinline__ float redmax16(float v) {
    v = fmaxf(v, __shfl_xor_sync(FULLMASK, v, 8));
    v = fmaxf(v, __shfl_xor_sync(FULLMASK, v, 4));
    v = fmaxf(v, __shfl_xor_sync(FULLMASK, v, 2));
    v = fmaxf(v, __shfl_xor_sync(FULLMASK, v, 1));
    return v;
}

// Issue 16 cp.async (each = 32 lanes x 16B = 512B) copying one 8KB patch tile
// gmem -> smem identity layout, then commit the group. Zero register cost:
// the epilogue of the PREVIOUS patch runs while this data streams in.
__device__ __forceinline__ void prefetch_patch(
    unsigned smem_dst, const float* gsrc, int lane)
{
#pragma unroll
    for (int t = 0; t < 16; t++) {
        const unsigned d = smem_dst + t * 512 + lane * 16;
        const float* s = gsrc + t * 128 + lane * 4;
        asm volatile("cp.async.cg.shared.global [%0], [%1], 16;"
                     :: "r"(d), "l"(s) : "memory");
    }
    asm volatile("cp.async.commit_group;" ::: "memory");
}

// One warp : PATCHES_PER_WARP patches, double-buffered cp.async pipeline.
// Block = 128 threads (4 warps); dynamic smem = 4 warps x 2 x 8KB = 64KB
// -> 3 CTAs/SM, 12 warps each with 8KB permanently in flight.
__global__ void __launch_bounds__(128) router_kernel(
    const float* __restrict__ patch,
    const float* __restrict__ keys,
    const float* __restrict__ p_temp,
    const float* __restrict__ p_beta,
    const float* __restrict__ p_thr,
    float* __restrict__ out,
    int n_patches)
{
    extern __shared__ float dynbuf[];           // [4 warps][2 bufs][2048 floats]
    __shared__ float s_keys[16 * 33];           // stride-33 pad: conflict-free
    __shared__ float s_raw[4][32];              // per-warp channel sums

    const int tid  = threadIdx.x;
    const int wid  = tid >> 5;
    const int lane = tid & 31;

    for (int i = tid; i < 16 * 32; i += 128)
        s_keys[(i >> 5) * 33 + (i & 31)] = keys[i];
    __syncthreads();

    const int n0 = (blockIdx.x * 4 + wid) * PATCHES_PER_WARP;
    if (n0 >= n_patches) return;                 // warp-uniform

    const float logit_temp = __ldg(p_temp);
    const float mask_beta  = __ldg(p_beta);
    const float thr_base   = __ldg(p_thr);
    const int e = lane & 15;

    float* mybuf = dynbuf + wid * 4096;          // 2 x 2048 floats
    unsigned buf_u32[2];
    buf_u32[0] = (unsigned)__cvta_generic_to_shared(mybuf);
    buf_u32[1] = buf_u32[0] + 8192;

    // Cold-start: prefetch first patch
    prefetch_patch(buf_u32[0], patch + (size_t)n0 * 2048, lane);

#pragma unroll 1
    for (int i = 0; i < PATCHES_PER_WARP; i++) {
        const int n = n0 + i;
        if (n >= n_patches) break;               // warp-uniform

        const bool more = (i + 1 < PATCHES_PER_WARP) && (n + 1 < n_patches);
        if (more)
            prefetch_patch(buf_u32[(i + 1) & 1], patch + (size_t)(n + 1) * 2048, lane);

        // Wait for current tile (leave the just-issued group in flight)
        if (more) asm volatile("cp.async.wait_group 1;" ::: "memory");
        else      asm volatile("cp.async.wait_group 0;" ::: "memory");
        __syncwarp();

        // ---- Reduce tile -> 32 channel sums (grouped mapping, LDS) ----
        const float4* tile = reinterpret_cast<const float4*>(mybuf + (i & 1) * 2048);
#pragma unroll
        for (int p = 0; p < 4; p++) {
            float a = 0.0f;
#pragma unroll
            for (int q = 0; q < 4; q++) {
                const float4 x = tile[p * 128 + (lane >> 2) * 16 + (lane & 3) + 4 * q];
                a += (x.x + x.y) + (x.z + x.w);
            }
            a += __shfl_xor_sync(FULLMASK, a, 1);
            a += __shfl_xor_sync(FULLMASK, a, 2);
            if ((lane & 3) == 0)
                s_raw[wid][p * 8 + (lane >> 2)] = a;    // raw sum (mean*64)
        }
        __syncwarp();

        // ---- Epilogue (R1-verified); overlaps next patch's cp.async DMA ----
        const float rc = s_raw[wid][lane];
        float sq = rc * rc;
        sq += __shfl_xor_sync(FULLMASK, sq, 16);
        sq += __shfl_xor_sync(FULLMASK, sq, 8);
        sq += __shfl_xor_sync(FULLMASK, sq, 4);
        sq += __shfl_xor_sync(FULLMASK, sq, 2);
        sq += __shfl_xor_sync(FULLMASK, sq, 1);
        const float denom = fmaxf(sqrtf(sq), 64.0f * 1e-12f);

        float dot = 0.0f;
#pragma unroll
        for (int c = 0; c < 32; c++)
            dot = fmaf(s_raw[wid][c], s_keys[e * 33 + c], dot);

        const float sl = (dot / denom) / logit_temp + 1e-8f;

        const float m  = redmax16(sl);
        const float ex = __expf(sl - m);
        const float S  = redsum16(ex);
        const float w  = ex / S;

        int rank = 0;
#pragma unroll
        for (int j = 0; j < 16; j++) {
            const float wj = __shfl_sync(FULLMASK, w, j, 16);
            rank += (wj > w) || (wj == w && j < e);
        }

        const float s0    = redsum16(rank == 0 ? w : 0.0f);
        const float rest  = redsum16((rank >= 1 && rank <= 4) ? w : 0.0f) * 0.25f;
        const float kth   = redsum16(rank == 3 ? w : 0.0f);
        const float meanw = redsum16(w) * (1.0f / 16.0f);
        const float dd    = w - meanw;
        const float varw  = redsum16(dd * dd) * (1.0f / 15.0f);
        const float stdw  = sqrtf(varw);
        const float ent   = -redsum16(w * __logf(w + 1e-18f));

        const float maxc = 1.0f - s0;
        const float entc = 1.0f - ent * (1.0f / 2.7725887222397811f);  // 1/log16
        float gap = (s0 - rest) / (s0 + 1e-8f);
        gap = fminf(fmaxf(gap, 0.0f), 1.0f);
        const float af = 0.4f * maxc + 0.3f * entc + 0.3f * gap;
        float adaptive = thr_base * (0.5f + af);
        const float min_thr = fmaxf(0.05f, meanw - 0.5f * stdw);
        const float max_thr = fminf(0.7f, s0 - 0.1f * stdw);
        adaptive = fminf(fmaxf(adaptive, min_thr), max_thr);
        adaptive = fminf(adaptive, kth * 0.9f);

        const float xx  = (mask_beta + 1e-8f) * (w - adaptive);
        const float sm  = 1.0f / (1.0f + __expf(-xx));
        const float wf  = w * sm;
        const float swf = redsum16(wf);
        const float o   = wf / fmaxf(swf, 1e-8f);

        if (lane < 16)
            out[(size_t)n * 16 + e] = o;
        __syncwarp();   // s_raw fully consumed before next iteration's reduce
    }
}

extern "C" void kernel_launch(void* const* d_in, const int* in_sizes, int n_in,
                              void* d_out, int out_size) {
    const float* patch = (const float*)d_in[0];
    const float* keys  = (const float*)d_in[1];
    const float* temp  = (const float*)d_in[2];
    const float* beta  = (const float*)d_in[3];
    const float* thr   = (const float*)d_in[4];
    float* out = (float*)d_out;

    const int n_patches = in_sizes[0] / (32 * 8 * 8);

    const int smem_bytes = 4 * 2 * 2048 * sizeof(float);   // 64KB dynamic
    static int configured = 0;
    if (!configured) {
        cudaFuncSetAttribute(router_kernel,
                             cudaFuncAttributeMaxDynamicSharedMemorySize, smem_bytes);
        configured = 1;
    }

    const int patches_per_block = 4 * PATCHES_PER_WARP;    // 32
    const int blocks = (n_patches + patches_per_block - 1) / patches_per_block;
    router_kernel<<<blocks, 128, smem_bytes>>>(patch, keys, temp, beta, thr,
                                               out, n_patches);
}

// round 17
// speedup vs baseline: 1.4328x; 1.2953x over previous
#include <cuda_runtime.h>

#define FULLMASK 0xffffffffu

__device__ __forceinline__ float redsum16(float v) {
    v += __shfl_xor_sync(FULLMASK, v, 8);
    v += __shfl_xor_sync(FULLMASK, v, 4);
    v += __shfl_xor_sync(FULLMASK, v, 2);
    v += __shfl_xor_sync(FULLMASK, v, 1);
    return v;
}
__device__ __forceinline__ float redmax16(float v) {
    v = fmaxf(v, __shfl_xor_sync(FULLMASK, v, 8));
    v = fmaxf(v, __shfl_xor_sync(FULLMASK, v, 4));
    v = fmaxf(v, __shfl_xor_sync(FULLMASK, v, 2));
    v = fmaxf(v, __shfl_xor_sync(FULLMASK, v, 1));
    return v;
}

// Monolithic 1-warp-per-patch (proven 51.7us structure) with a slimmed
// epilogue (~240 -> ~145 warp-inst/patch):
//  * keys live in registers: lane (e, half) holds k[e][half*16 .. +16); the
//    expert dot is split across mirrored halves (16 LDS + 16 FMA + 1 shfl
//    instead of 64 LDS + 32 FMA).
//  * top-5 via 5 max-extraction rounds (redmax+ballot+ffs) replacing the
//    16-shfl rank loop + 3 masked reductions.
//  * meanw = 1/16 exactly (softmax weights sum to 1).
__global__ void __launch_bounds__(256) router_kernel(
    const float* __restrict__ patch,
    const float* __restrict__ keys,
    const float* __restrict__ p_temp,
    const float* __restrict__ p_beta,
    const float* __restrict__ p_thr,
    float* __restrict__ out,
    int n_patches)
{
    __shared__ float s_keys[16 * 36];   // row stride 36 floats (bank-spread)
    __shared__ float s_raw[8][32];      // per-warp channel sums

    const int tid  = threadIdx.x;
    const int wid  = tid >> 5;
    const int lane = tid & 31;

    for (int i = tid; i < 16 * 32; i += 256)
        s_keys[(i >> 5) * 36 + (i & 31)] = keys[i];
    __syncthreads();

    const int n = blockIdx.x * 8 + wid;
    if (n >= n_patches) return;          // warp-uniform; no block syncs below

    const float logit_temp = __ldg(p_temp);
    const float mask_beta  = __ldg(p_beta);
    const float thr_base   = __ldg(p_thr);

    const int e    = lane & 15;          // expert
    const int half = lane & 16;          // which 16 channels this lane covers

    // ---- Keys to registers: this lane's half-row of expert e (4 x LDS.128) ----
    float4 kr[4];
    {
        const float4* kp = reinterpret_cast<const float4*>(s_keys + e * 36 + half);
#pragma unroll
        for (int j = 0; j < 4; j++) kr[j] = kp[j];
    }

    // ---- Streaming load + reduce (R1 grouped pattern: 8 shfl total) ----
    const float4* p4 = reinterpret_cast<const float4*>(patch) + (size_t)n * 512;
    float4 v[16];
#pragma unroll
    for (int t = 0; t < 16; t++) {
        const int p = t >> 2, q = t & 3;
        v[t] = p4[p * 128 + (lane >> 2) * 16 + (lane & 3) + 4 * q];
    }
#pragma unroll
    for (int p = 0; p < 4; p++) {
        float a = 0.0f;
#pragma unroll
        for (int q = 0; q < 4; q++) {
            const float4 x = v[p * 4 + q];
            a += (x.x + x.y) + (x.z + x.w);
        }
        a += __shfl_xor_sync(FULLMASK, a, 1);
        a += __shfl_xor_sync(FULLMASK, a, 2);
        if ((lane & 3) == 0)
            s_raw[wid][p * 8 + (lane >> 2)] = a;   // raw channel sum (mean*64)
    }
    __syncwarp();

    // ---- L2 norm (5 shfl) ----
    const float rc = s_raw[wid][lane];
    float sq = rc * rc;
    sq += __shfl_xor_sync(FULLMASK, sq, 16);
    sq += __shfl_xor_sync(FULLMASK, sq, 8);
    sq += __shfl_xor_sync(FULLMASK, sq, 4);
    sq += __shfl_xor_sync(FULLMASK, sq, 2);
    sq += __shfl_xor_sync(FULLMASK, sq, 1);
    const float denom = fmaxf(sqrtf(sq), 64.0f * 1e-12f);

    // ---- Half-split expert dot: 16 broadcast LDS + 16 reg-FMA + 1 fold ----
    float dot = 0.0f;
#pragma unroll
    for (int j = 0; j < 4; j++) {
        const float4 k = kr[j];
        dot = fmaf(s_raw[wid][half + j * 4 + 0], k.x, dot);
        dot = fmaf(s_raw[wid][half + j * 4 + 1], k.y, dot);
        dot = fmaf(s_raw[wid][half + j * 4 + 2], k.z, dot);
        dot = fmaf(s_raw[wid][half + j * 4 + 3], k.w, dot);
    }
    dot += __shfl_xor_sync(FULLMASK, dot, 16);    // both halves now full dot

    const float sl = (dot / denom) / logit_temp + 1e-8f;

    // ---- Softmax over 16 ----
    const float m  = redmax16(sl);
    const float ex = __expf(sl - m);
    const float S  = redsum16(ex);
    const float w  = ex / S;

    // ---- Top-5 values via 5 max-extractions (replaces rank loop) ----
    float cur = w;
    float top[5];
#pragma unroll
    for (int k = 0; k < 5; k++) {
        const float mx = redmax16(cur);
        top[k] = mx;
        const unsigned b = __ballot_sync(FULLMASK, cur == mx) & 0xFFFFu;
        const int victim = __ffs(b) - 1;          // lowest expert idx holding mx
        if (e == victim) cur = -1.0f;             // remove one instance (both halves)
    }
    const float s0   = top[0];
    const float rest = (top[1] + top[2] + top[3] + top[4]) * 0.25f;
    const float kth  = top[3];                    // 4th largest

    // ---- Moments & entropy (meanw = 1/16 exactly: softmax sums to 1) ----
    const float meanw = 0.0625f;
    const float d     = w - meanw;
    const float varw  = redsum16(d * d) * (1.0f / 15.0f);    // ddof=1
    const float stdw  = sqrtf(varw);
    const float ent   = -redsum16(w * __logf(w + 1e-18f));

    // ---- Adaptive threshold ----
    const float maxc = 1.0f - s0;
    const float entc = 1.0f - ent * (1.0f / 2.7725887222397811f);   // 1/log(16)
    float gap = (s0 - rest) / (s0 + 1e-8f);
    gap = fminf(fmaxf(gap, 0.0f), 1.0f);
    const float af = 0.4f * maxc + 0.3f * entc + 0.3f * gap;
    float adaptive = thr_base * (0.5f + af);
    const float min_thr = fmaxf(0.05f, meanw - 0.5f * stdw);
    const float max_thr = fminf(0.7f, s0 - 0.1f * stdw);
    adaptive = fminf(fmaxf(adaptive, min_thr), max_thr);
    adaptive = fminf(adaptive, kth * 0.9f);

    // ---- Soft mask + renormalize ----
    const float x    = (mask_beta + 1e-8f) * (w - adaptive);
    const float sm   = 1.0f / (1.0f + __expf(-x));
    const float wf   = w * sm;
    const float swf  = redsum16(wf);
    const float o    = wf / fmaxf(swf, 1e-8f);

    if (lane < 16)
        out[(size_t)n * 16 + e] = o;
}

extern "C" void kernel_launch(void* const* d_in, const int* in_sizes, int n_in,
                              void* d_out, int out_size) {
    const float* patch = (const float*)d_in[0];
    const float* keys  = (const float*)d_in[1];
    const float* temp  = (const float*)d_in[2];
    const float* beta  = (const float*)d_in[3];
    const float* thr   = (const float*)d_in[4];
    float* out = (float*)d_out;

    const int n_patches = in_sizes[0] / (32 * 8 * 8);
    const int blocks = (n_patches + 7) / 8;   // 8 warps (patches) per block
    router_kernel<<<blocks, 256>>>(patch, keys, temp, beta, thr, out, n_patches);
}